// round 15
// baseline (speedup 1.0000x reference)
#include <cuda_runtime.h>
#include <cuda_bf16.h>
#include <cstdint>

// Problem constants
#define N_NODES 8192
#define NFEAT   1024
#define NHID    512
#define OUTD    256
#define BN_EPS  1e-5f

// Intermediates (allocation-free rule: device globals)
__device__ float g_S1[N_NODES * NHID];   // x @ W1
__device__ float g_H [N_NODES * NHID];   // relu(IFadj@S1 + b1)
__device__ float g_S2[N_NODES * OUTD];   // H @ W2

// ---------------------------------------------------------------------------
// helpers
// ---------------------------------------------------------------------------
__device__ __forceinline__ uint32_t smem_u32(const void* p) {
    uint32_t a;
    asm("{ .reg .u64 t; cvta.to.shared.u64 t, %1; cvt.u32.u64 %0, t; }"
        : "=r"(a) : "l"(p));
    return a;
}

// Swizzles (conflict-free ldmatrix):
// A tile: 128 rows x 128B (64 bf16 k). classic SW128: bits[4:6] ^= bits[7:9]
__device__ __forceinline__ uint32_t sw_a(uint32_t o) { return o ^ ((o >> 3) & 0x70); }
// B tile: 64 rows x 256B (128 bf16 n). bits[4:6] ^= bits[8:10]
__device__ __forceinline__ uint32_t sw_b(uint32_t o) { return o ^ ((o >> 4) & 0x70); }

__device__ __forceinline__ void ldsm_x4(uint32_t r[4], uint32_t addr) {
    asm volatile("ldmatrix.sync.aligned.m8n8.x4.shared.b16 {%0,%1,%2,%3}, [%4];"
        : "=r"(r[0]), "=r"(r[1]), "=r"(r[2]), "=r"(r[3]) : "r"(addr));
}
__device__ __forceinline__ void ldsm_x4_t(uint32_t r[4], uint32_t addr) {
    asm volatile("ldmatrix.sync.aligned.m8n8.x4.trans.shared.b16 {%0,%1,%2,%3}, [%4];"
        : "=r"(r[0]), "=r"(r[1]), "=r"(r[2]), "=r"(r[3]) : "r"(addr));
}

__device__ __forceinline__ void mma_bf16(float* c, const uint32_t a[4],
                                         uint32_t b0, uint32_t b1) {
    asm volatile(
        "mma.sync.aligned.m16n8k16.row.col.f32.bf16.bf16.f32 "
        "{%0,%1,%2,%3}, {%4,%5,%6,%7}, {%8,%9}, {%0,%1,%2,%3};"
        : "+f"(c[0]), "+f"(c[1]), "+f"(c[2]), "+f"(c[3])
        : "r"(a[0]), "r"(a[1]), "r"(a[2]), "r"(a[3]), "r"(b0), "r"(b1));
}

// fp32 pair -> (hi, lo) bf16x2
__device__ __forceinline__ void split_pack(float a, float b, uint32_t& hi, uint32_t& lo) {
    __nv_bfloat162 h = __floats2bfloat162_rn(a, b);
    float ra = a - __bfloat162float(h.x);
    float rb = b - __bfloat162float(h.y);
    __nv_bfloat162 l = __floats2bfloat162_rn(ra, rb);
    hi = *reinterpret_cast<uint32_t*>(&h);
    lo = *reinterpret_cast<uint32_t*>(&l);
}

// ---------------------------------------------------------------------------
// Warp-specialized split-precision bf16 mma.sync GEMM.
// C[M,N] = A[M,K] @ B[K,N] (fp32 in/out).
// CTA tile 128x128, BK=64 (fewer barrier-delimited chunks -> fixed per-chunk
// overhead amortized over 2x the MMA work), 512 threads:
//   warps 0-7 : CONSUMERS, warp tile 64x32 (2M x 4N), LDSM + MMA + epilogue
//   warps 8-15: PRODUCERS, LDG fp32 -> split hi/lo bf16 -> STS
// Double-buffered SMEM (2 x 64KB = 128KB), one __syncthreads per K-chunk.
// 3 MMA products: Ah*Bh + Al*Bh + Ah*Bl (lo*lo dropped).
// EPI 0: none | 1: relu(+bias) | 2: BatchNorm eval (+bias)
// ---------------------------------------------------------------------------
#define STAGE_BYTES 65536   // Ahi 16K | Alo 16K | Bhi 16K | Blo 16K

template<int EPI>
__global__ __launch_bounds__(512, 1)
void mma_gemm(const float* __restrict__ A, const float* __restrict__ B,
              float* __restrict__ C, int M, int N, int K,
              const float* __restrict__ bias,
              const float* __restrict__ bng, const float* __restrict__ bnb,
              const float* __restrict__ bnm, const float* __restrict__ bnv)
{
    extern __shared__ __align__(128) char smc[];   // 128 KB: 2 stages
    const uint32_t sbase = smem_u32(smc);

    const int tid  = threadIdx.x;
    const int lane = tid & 31;
    const int wid  = tid >> 5;
    const bool is_consumer = (wid < 8);
    const int rowBase = blockIdx.y * 128;
    const int colBase = blockIdx.x * 128;
    const int nk = K >> 6;   // K / 64

    if (!is_consumer) {
        // =========================== PRODUCER ===============================
        const int ptid = tid - 256;            // 0..255
        float4 stA[8];                          // A: 128m x 64k fp32 (1/256 each)
        float4 stB[4][2];                       // B: 64k x 128n fp32

        auto ldg = [&](int k0) {
#pragma unroll
            for (int s = 0; s < 8; s++) {
                const int idx = (ptid + s * 256) * 4;
                const int m = idx >> 6, k = idx & 63;
                stA[s] = *reinterpret_cast<const float4*>(
                    A + (size_t)(rowBase + m) * K + k0 + k);
            }
#pragma unroll
            for (int s = 0; s < 4; s++) {
                const int idx = (ptid + s * 256) * 8;
                const int k = idx >> 7, n = idx & 127;
                const float* p = B + (size_t)(k0 + k) * N + colBase + n;
                stB[s][0] = *reinterpret_cast<const float4*>(p);
                stB[s][1] = *reinterpret_cast<const float4*>(p + 4);
            }
        };

        auto sts = [&](int buf) {
            char* base = smc + buf * STAGE_BYTES;
#pragma unroll
            for (int s = 0; s < 8; s++) {
                const int idx = (ptid + s * 256) * 4;
                const int m = idx >> 6, k = idx & 63;
                uint32_t h0, l0, h1, l1;
                split_pack(stA[s].x, stA[s].y, h0, l0);
                split_pack(stA[s].z, stA[s].w, h1, l1);
                const uint32_t off = sw_a((uint32_t)(m * 128 + k * 2)); // 8B aligned
                *reinterpret_cast<uint2*>(base + off)         = make_uint2(h0, h1);
                *reinterpret_cast<uint2*>(base + 16384 + off) = make_uint2(l0, l1);
            }
#pragma unroll
            for (int s = 0; s < 4; s++) {
                const int idx = (ptid + s * 256) * 8;
                const int k = idx >> 7, n = idx & 127;
                uint32_t h[4], l[4];
                split_pack(stB[s][0].x, stB[s][0].y, h[0], l[0]);
                split_pack(stB[s][0].z, stB[s][0].w, h[1], l[1]);
                split_pack(stB[s][1].x, stB[s][1].y, h[2], l[2]);
                split_pack(stB[s][1].z, stB[s][1].w, h[3], l[3]);
                const uint32_t off = sw_b((uint32_t)(k * 256 + n * 2)); // 16B aligned
                *reinterpret_cast<uint4*>(base + 32768 + off) = make_uint4(h[0], h[1], h[2], h[3]);
                *reinterpret_cast<uint4*>(base + 49152 + off) = make_uint4(l[0], l[1], l[2], l[3]);
            }
        };

        ldg(0);
        sts(0);
        __syncthreads();
        for (int it = 0; it < nk; it++) {
            if (it + 1 < nk) {
                ldg((it + 1) << 6);
                sts((it + 1) & 1);   // other buffer: consumers read it&1 now
            }
            __syncthreads();
        }
        return;   // producers skip the epilogue
    }

    // ============================= CONSUMER ==================================
    const int wm = (wid >> 2) * 64;    // warp M offset (0 or 64)
    const int wn = (wid & 3) * 32;     // warp N offset (0/32/64/96)

    float acc[4][4][4];                 // 4 m-frags x 4 n-frags x 4 regs = 64
#pragma unroll
    for (int i = 0; i < 4; i++)
#pragma unroll
        for (int j = 0; j < 4; j++)
#pragma unroll
            for (int r = 0; r < 4; r++) acc[i][j][r] = 0.f;

    __syncthreads();   // matches producers' post-prologue barrier
    for (int it = 0; it < nk; it++) {
        const int buf = it & 1;
        const uint32_t sA_hi = sbase + buf * STAGE_BYTES;
        const uint32_t sA_lo = sA_hi + 16384;
        const uint32_t sB_hi = sA_hi + 32768;
        const uint32_t sB_lo = sA_hi + 49152;

#pragma unroll
        for (int ks = 0; ks < 4; ks++) {
            const int k0 = ks * 16;
            // A fragments hi+lo: 4 m-frags of 16x16
            uint32_t af[2][4][4];
            {
                const int m_lane = lane & 15;
                const int k_lane = k0 + ((lane >> 4) << 3);
#pragma unroll
                for (int mf = 0; mf < 4; mf++) {
                    const uint32_t off = sw_a(
                        (uint32_t)((wm + mf * 16 + m_lane) * 128 + k_lane * 2));
                    ldsm_x4(af[0][mf], sA_hi + off);
                    ldsm_x4(af[1][mf], sA_lo + off);
                }
            }
            // B fragments: 2 trans groups cover 32 n (4 n-frags)
            const int mat = lane >> 3, wi = lane & 7;
            const int k_lane = k0 + (mat & 1) * 8 + wi;
            uint32_t bfr[2][4];
#pragma unroll
            for (int grp = 0; grp < 2; grp++) {
                const int n_lane = wn + grp * 16 + (mat >> 1) * 8;
                ldsm_x4_t(bfr[grp], sB_hi + sw_b((uint32_t)(k_lane * 256 + n_lane * 2)));
            }
            // block 1: Ah*Bh over all 16 accumulators
#pragma unroll
            for (int mf = 0; mf < 4; mf++)
#pragma unroll
                for (int nf = 0; nf < 4; nf++) {
                    const int g = nf >> 1, q = (nf & 1) * 2;
                    mma_bf16(acc[mf][nf], af[0][mf], bfr[g][q], bfr[g][q + 1]);
                }
            // block 2: Al*Bh
#pragma unroll
            for (int mf = 0; mf < 4; mf++)
#pragma unroll
                for (int nf = 0; nf < 4; nf++) {
                    const int g = nf >> 1, q = (nf & 1) * 2;
                    mma_bf16(acc[mf][nf], af[1][mf], bfr[g][q], bfr[g][q + 1]);
                }
            // reload B = Blo, block 3: Ah*Bl
#pragma unroll
            for (int grp = 0; grp < 2; grp++) {
                const int n_lane = wn + grp * 16 + (mat >> 1) * 8;
                ldsm_x4_t(bfr[grp], sB_lo + sw_b((uint32_t)(k_lane * 256 + n_lane * 2)));
            }
#pragma unroll
            for (int mf = 0; mf < 4; mf++)
#pragma unroll
                for (int nf = 0; nf < 4; nf++) {
                    const int g = nf >> 1, q = (nf & 1) * 2;
                    mma_bf16(acc[mf][nf], af[0][mf], bfr[g][q], bfr[g][q + 1]);
                }
        }
        __syncthreads();
    }

    // ---- epilogue (consumers only) ----
    const int g   = lane >> 2;
    const int tig = lane & 3;
#pragma unroll
    for (int mf = 0; mf < 4; mf++) {
#pragma unroll
        for (int nf = 0; nf < 4; nf++) {
            const int row = rowBase + wm + mf * 16 + g;
            const int col = colBase + wn + nf * 8 + tig * 2;
            float v0 = acc[mf][nf][0], v1 = acc[mf][nf][1];
            float v2 = acc[mf][nf][2], v3 = acc[mf][nf][3];
            if constexpr (EPI >= 1) {
                const float b0 = bias[col], b1 = bias[col + 1];
                v0 += b0; v1 += b1; v2 += b0; v3 += b1;
            }
            if constexpr (EPI == 1) {
                v0 = fmaxf(v0, 0.f); v1 = fmaxf(v1, 0.f);
                v2 = fmaxf(v2, 0.f); v3 = fmaxf(v3, 0.f);
            }
            if constexpr (EPI == 2) {
                const float i0 = bng[col]     * rsqrtf(bnv[col]     + BN_EPS);
                const float i1 = bng[col + 1] * rsqrtf(bnv[col + 1] + BN_EPS);
                const float a0 = bnb[col]     - bnm[col]     * i0;
                const float a1 = bnb[col + 1] - bnm[col + 1] * i1;
                v0 = v0 * i0 + a0; v1 = v1 * i1 + a1;
                v2 = v2 * i0 + a0; v3 = v3 * i1 + a1;
            }
            *reinterpret_cast<float2*>(C + (size_t)row * N + col)       = make_float2(v0, v1);
            *reinterpret_cast<float2*>(C + (size_t)(row + 8) * N + col) = make_float2(v2, v3);
        }
    }
}

// ---------------------------------------------------------------------------
extern "C" void kernel_launch(void* const* d_in, const int* in_sizes, int n_in,
                              void* d_out, int out_size)
{
    const float* x     = (const float*)d_in[0];
    const float* IFadj = (const float*)d_in[1];
    const float* adj   = (const float*)d_in[2];
    const float* W1    = (const float*)d_in[3];
    const float* b1    = (const float*)d_in[4];
    const float* W2    = (const float*)d_in[5];
    const float* b2    = (const float*)d_in[6];
    const float* bng   = (const float*)d_in[7];
    const float* bnb   = (const float*)d_in[8];
    const float* bnm   = (const float*)d_in[9];
    const float* bnv   = (const float*)d_in[10];
    float* out = (float*)d_out;

    float *s1, *h, *s2;
    cudaGetSymbolAddress((void**)&s1, g_S1);
    cudaGetSymbolAddress((void**)&h,  g_H);
    cudaGetSymbolAddress((void**)&s2, g_S2);

    const int smem = 2 * STAGE_BYTES;   // 128 KB dynamic
    cudaFuncSetAttribute(mma_gemm<0>, cudaFuncAttributeMaxDynamicSharedMemorySize, smem);
    cudaFuncSetAttribute(mma_gemm<1>, cudaFuncAttributeMaxDynamicSharedMemorySize, smem);
    cudaFuncSetAttribute(mma_gemm<2>, cudaFuncAttributeMaxDynamicSharedMemorySize, smem);

    const dim3 blk(512);

    // 1) S1 = x @ W1                      M=8192 N=512 K=1024
    mma_gemm<0><<<dim3(NHID / 128, N_NODES / 128), blk, smem>>>(
        x, W1, s1, N_NODES, NHID, NFEAT, nullptr, nullptr, nullptr, nullptr, nullptr);

    // 2) H = relu(IFadj @ S1 + b1)        M=8192 N=512 K=8192  (dominant)
    mma_gemm<1><<<dim3(NHID / 128, N_NODES / 128), blk, smem>>>(
        IFadj, s1, h, N_NODES, NHID, N_NODES, b1, nullptr, nullptr, nullptr, nullptr);

    // 3) S2 = H @ W2                      M=8192 N=256 K=512
    mma_gemm<0><<<dim3(OUTD / 128, N_NODES / 128), blk, smem>>>(
        h, W2, s2, N_NODES, OUTD, NHID, nullptr, nullptr, nullptr, nullptr, nullptr);

    // 4) out = BN(adj @ S2 + b2)          M=8192 N=256 K=8192
    mma_gemm<2><<<dim3(OUTD / 128, N_NODES / 128), blk, smem>>>(
        adj, s2, out, N_NODES, OUTD, N_NODES, b2, bng, bnb, bnm, bnv);
}

// round 16
// speedup vs baseline: 1.0619x; 1.0619x over previous
#include <cuda_runtime.h>
#include <cuda_bf16.h>
#include <cstdint>

// Problem constants
#define N_NODES 8192
#define NFEAT   1024
#define NHID    512
#define OUTD    256
#define BN_EPS  1e-5f

// Intermediates (allocation-free rule: device globals)
__device__ float g_S1[N_NODES * NHID];   // x @ W1
__device__ float g_H [N_NODES * NHID];   // relu(IFadj@S1 + b1)
__device__ float g_S2[N_NODES * OUTD];   // H @ W2

// ---------------------------------------------------------------------------
// helpers
// ---------------------------------------------------------------------------
__device__ __forceinline__ uint32_t smem_u32(const void* p) {
    uint32_t a;
    asm("{ .reg .u64 t; cvta.to.shared.u64 t, %1; cvt.u32.u64 %0, t; }"
        : "=r"(a) : "l"(p));
    return a;
}

// Swizzles (conflict-free ldmatrix):
// A tile: 128 rows x 128B (64 bf16 k). classic SW128: bits[4:6] ^= bits[7:9]
__device__ __forceinline__ uint32_t sw_a(uint32_t o) { return o ^ ((o >> 3) & 0x70); }
// B tile: 64 rows x 256B (128 bf16 n). bits[4:6] ^= bits[8:10]
__device__ __forceinline__ uint32_t sw_b(uint32_t o) { return o ^ ((o >> 4) & 0x70); }

__device__ __forceinline__ void ldsm_x4(uint32_t r[4], uint32_t addr) {
    asm volatile("ldmatrix.sync.aligned.m8n8.x4.shared.b16 {%0,%1,%2,%3}, [%4];"
        : "=r"(r[0]), "=r"(r[1]), "=r"(r[2]), "=r"(r[3]) : "r"(addr));
}
__device__ __forceinline__ void ldsm_x4_t(uint32_t r[4], uint32_t addr) {
    asm volatile("ldmatrix.sync.aligned.m8n8.x4.trans.shared.b16 {%0,%1,%2,%3}, [%4];"
        : "=r"(r[0]), "=r"(r[1]), "=r"(r[2]), "=r"(r[3]) : "r"(addr));
}

__device__ __forceinline__ void mma_bf16(float* c, const uint32_t a[4],
                                         uint32_t b0, uint32_t b1) {
    asm volatile(
        "mma.sync.aligned.m16n8k16.row.col.f32.bf16.bf16.f32 "
        "{%0,%1,%2,%3}, {%4,%5,%6,%7}, {%8,%9}, {%0,%1,%2,%3};"
        : "+f"(c[0]), "+f"(c[1]), "+f"(c[2]), "+f"(c[3])
        : "r"(a[0]), "r"(a[1]), "r"(a[2]), "r"(a[3]), "r"(b0), "r"(b1));
}

// fp32 pair -> (hi, lo) bf16x2
__device__ __forceinline__ void split_pack(float a, float b, uint32_t& hi, uint32_t& lo) {
    __nv_bfloat162 h = __floats2bfloat162_rn(a, b);
    float ra = a - __bfloat162float(h.x);
    float rb = b - __bfloat162float(h.y);
    __nv_bfloat162 l = __floats2bfloat162_rn(ra, rb);
    hi = *reinterpret_cast<uint32_t*>(&h);
    lo = *reinterpret_cast<uint32_t*>(&l);
}

// ---------------------------------------------------------------------------
// Warp-specialized split-precision bf16 mma.sync GEMM with REGISTER-LEVEL
// FRAGMENT DOUBLE-BUFFERING: k-step ks+1's 12 LDSMs are issued before
// k-step ks's 48 MMAs, hiding LDSM latency under the MMA burst (the
// LDSM->MMA serialization that pinned tensor% at ~59% across R9-R14).
// C[M,N] = A[M,K] @ B[K,N] (fp32 in/out).
// CTA tile 128x128, BK=64 (4 k-steps: 3/4 of LDSM chains covered), 512 thr:
//   warps 0-7 : CONSUMERS, warp tile 64x32 (2M x 4N)
//   warps 8-15: PRODUCERS, LDG fp32 -> split hi/lo bf16 -> STS
// Double-buffered SMEM (2 x 64KB), one __syncthreads per K-chunk.
// 3 MMA products: Ah*Bh + Al*Bh + Ah*Bl (lo*lo dropped).
// EPI 0: none | 1: relu(+bias) | 2: BatchNorm eval (+bias)
// ---------------------------------------------------------------------------
#define STAGE_BYTES 65536   // Ahi 16K | Alo 16K | Bhi 16K | Blo 16K

template<int EPI>
__global__ __launch_bounds__(512, 1)
void mma_gemm(const float* __restrict__ A, const float* __restrict__ B,
              float* __restrict__ C, int M, int N, int K,
              const float* __restrict__ bias,
              const float* __restrict__ bng, const float* __restrict__ bnb,
              const float* __restrict__ bnm, const float* __restrict__ bnv)
{
    extern __shared__ __align__(128) char smc[];   // 128 KB: 2 stages
    const uint32_t sbase = smem_u32(smc);

    const int tid  = threadIdx.x;
    const int lane = tid & 31;
    const int wid  = tid >> 5;
    const bool is_consumer = (wid < 8);
    const int rowBase = blockIdx.y * 128;
    const int colBase = blockIdx.x * 128;
    const int nk = K >> 6;   // K / 64

    if (!is_consumer) {
        // =========================== PRODUCER ===============================
        const int ptid = tid - 256;            // 0..255
        float4 stA[8];                          // A: 128m x 64k fp32
        float4 stB[4][2];                       // B: 64k x 128n fp32

        auto ldg = [&](int k0) {
#pragma unroll
            for (int s = 0; s < 8; s++) {
                const int idx = (ptid + s * 256) * 4;
                const int m = idx >> 6, k = idx & 63;
                stA[s] = *reinterpret_cast<const float4*>(
                    A + (size_t)(rowBase + m) * K + k0 + k);
            }
#pragma unroll
            for (int s = 0; s < 4; s++) {
                const int idx = (ptid + s * 256) * 8;
                const int k = idx >> 7, n = idx & 127;
                const float* p = B + (size_t)(k0 + k) * N + colBase + n;
                stB[s][0] = *reinterpret_cast<const float4*>(p);
                stB[s][1] = *reinterpret_cast<const float4*>(p + 4);
            }
        };

        auto sts = [&](int buf) {
            char* base = smc + buf * STAGE_BYTES;
#pragma unroll
            for (int s = 0; s < 8; s++) {
                const int idx = (ptid + s * 256) * 4;
                const int m = idx >> 6, k = idx & 63;
                uint32_t h0, l0, h1, l1;
                split_pack(stA[s].x, stA[s].y, h0, l0);
                split_pack(stA[s].z, stA[s].w, h1, l1);
                const uint32_t off = sw_a((uint32_t)(m * 128 + k * 2)); // 8B aligned
                *reinterpret_cast<uint2*>(base + off)         = make_uint2(h0, h1);
                *reinterpret_cast<uint2*>(base + 16384 + off) = make_uint2(l0, l1);
            }
#pragma unroll
            for (int s = 0; s < 4; s++) {
                const int idx = (ptid + s * 256) * 8;
                const int k = idx >> 7, n = idx & 127;
                uint32_t h[4], l[4];
                split_pack(stB[s][0].x, stB[s][0].y, h[0], l[0]);
                split_pack(stB[s][0].z, stB[s][0].w, h[1], l[1]);
                split_pack(stB[s][1].x, stB[s][1].y, h[2], l[2]);
                split_pack(stB[s][1].z, stB[s][1].w, h[3], l[3]);
                const uint32_t off = sw_b((uint32_t)(k * 256 + n * 2)); // 16B aligned
                *reinterpret_cast<uint4*>(base + 32768 + off) = make_uint4(h[0], h[1], h[2], h[3]);
                *reinterpret_cast<uint4*>(base + 49152 + off) = make_uint4(l[0], l[1], l[2], l[3]);
            }
        };

        ldg(0);
        sts(0);
        __syncthreads();
        for (int it = 0; it < nk; it++) {
            if (it + 1 < nk) {
                ldg((it + 1) << 6);
                sts((it + 1) & 1);   // other buffer: consumers read it&1 now
            }
            __syncthreads();
        }
        return;   // producers skip the epilogue
    }

    // ============================= CONSUMER ==================================
    const int wm = (wid >> 2) * 64;    // warp M offset (0 or 64)
    const int wn = (wid & 3) * 32;     // warp N offset (0/32/64/96)

    float acc[4][4][4];                 // 64 regs
#pragma unroll
    for (int i = 0; i < 4; i++)
#pragma unroll
        for (int j = 0; j < 4; j++)
#pragma unroll
            for (int r = 0; r < 4; r++) acc[i][j][r] = 0.f;

    // Fragment double-buffer: [pb][...]  (af: A hi/lo, bh/bl: B hi/lo)
    uint32_t af[2][2][4][4];   // 64 regs
    uint32_t bh[2][2][4];      // 16 regs
    uint32_t bl[2][2][4];      // 16 regs

    // lane-constant addressing pieces
    const int m_lane   = lane & 15;
    const int ka_lane  = (lane >> 4) << 3;          // A: k sub-offset
    const int mat      = lane >> 3, wi = lane & 7;
    const int kb_lane  = (mat & 1) * 8 + wi;        // B: k sub-offset
    const int nb0      = wn + (mat >> 1) * 8;       // B: n base for grp 0

    __syncthreads();   // matches producers' post-prologue barrier
    for (int it = 0; it < nk; it++) {
        const int buf = it & 1;
        const uint32_t sA_hi = sbase + buf * STAGE_BYTES;
        const uint32_t sA_lo = sA_hi + 16384;
        const uint32_t sB_hi = sA_hi + 32768;
        const uint32_t sB_lo = sA_hi + 49152;

        // prefetch k-step 0 fragments into buffer 0
#pragma unroll
        for (int mf = 0; mf < 4; mf++) {
            const uint32_t off = sw_a(
                (uint32_t)((wm + mf * 16 + m_lane) * 128 + ka_lane * 2));
            ldsm_x4(af[0][0][mf], sA_hi + off);
            ldsm_x4(af[0][1][mf], sA_lo + off);
        }
#pragma unroll
        for (int grp = 0; grp < 2; grp++) {
            const uint32_t boff = sw_b(
                (uint32_t)(kb_lane * 256 + (nb0 + grp * 16) * 2));
            ldsm_x4_t(bh[0][grp], sB_hi + boff);
            ldsm_x4_t(bl[0][grp], sB_lo + boff);
        }

#pragma unroll
        for (int ks = 0; ks < 4; ks++) {
            const int pb = ks & 1;
            // prefetch NEXT k-step's fragments before this step's MMAs
            if (ks < 3) {
                const int nb = pb ^ 1;
                const int k1 = (ks + 1) * 16;
#pragma unroll
                for (int mf = 0; mf < 4; mf++) {
                    const uint32_t off = sw_a(
                        (uint32_t)((wm + mf * 16 + m_lane) * 128 + (k1 + ka_lane) * 2));
                    ldsm_x4(af[nb][0][mf], sA_hi + off);
                    ldsm_x4(af[nb][1][mf], sA_lo + off);
                }
#pragma unroll
                for (int grp = 0; grp < 2; grp++) {
                    const uint32_t boff = sw_b(
                        (uint32_t)((k1 + kb_lane) * 256 + (nb0 + grp * 16) * 2));
                    ldsm_x4_t(bh[nb][grp], sB_hi + boff);
                    ldsm_x4_t(bl[nb][grp], sB_lo + boff);
                }
            }
            // 48 MMAs on the CURRENT buffer (LDSMs above retire underneath)
#pragma unroll
            for (int mf = 0; mf < 4; mf++)
#pragma unroll
                for (int nf = 0; nf < 4; nf++) {
                    const int g = nf >> 1, q = (nf & 1) * 2;
                    mma_bf16(acc[mf][nf], af[pb][0][mf], bh[pb][g][q], bh[pb][g][q + 1]);
                }
#pragma unroll
            for (int mf = 0; mf < 4; mf++)
#pragma unroll
                for (int nf = 0; nf < 4; nf++) {
                    const int g = nf >> 1, q = (nf & 1) * 2;
                    mma_bf16(acc[mf][nf], af[pb][1][mf], bh[pb][g][q], bh[pb][g][q + 1]);
                }
#pragma unroll
            for (int mf = 0; mf < 4; mf++)
#pragma unroll
                for (int nf = 0; nf < 4; nf++) {
                    const int g = nf >> 1, q = (nf & 1) * 2;
                    mma_bf16(acc[mf][nf], af[pb][0][mf], bl[pb][g][q], bl[pb][g][q + 1]);
                }
        }
        __syncthreads();
    }

    // ---- epilogue (consumers only) ----
    const int g   = lane >> 2;
    const int tig = lane & 3;
#pragma unroll
    for (int mf = 0; mf < 4; mf++) {
#pragma unroll
        for (int nf = 0; nf < 4; nf++) {
            const int row = rowBase + wm + mf * 16 + g;
            const int col = colBase + wn + nf * 8 + tig * 2;
            float v0 = acc[mf][nf][0], v1 = acc[mf][nf][1];
            float v2 = acc[mf][nf][2], v3 = acc[mf][nf][3];
            if constexpr (EPI >= 1) {
                const float b0 = bias[col], b1 = bias[col + 1];
                v0 += b0; v1 += b1; v2 += b0; v3 += b1;
            }
            if constexpr (EPI == 1) {
                v0 = fmaxf(v0, 0.f); v1 = fmaxf(v1, 0.f);
                v2 = fmaxf(v2, 0.f); v3 = fmaxf(v3, 0.f);
            }
            if constexpr (EPI == 2) {
                const float i0 = bng[col]     * rsqrtf(bnv[col]     + BN_EPS);
                const float i1 = bng[col + 1] * rsqrtf(bnv[col + 1] + BN_EPS);
                const float a0 = bnb[col]     - bnm[col]     * i0;
                const float a1 = bnb[col + 1] - bnm[col + 1] * i1;
                v0 = v0 * i0 + a0; v1 = v1 * i1 + a1;
                v2 = v2 * i0 + a0; v3 = v3 * i1 + a1;
            }
            *reinterpret_cast<float2*>(C + (size_t)row * N + col)       = make_float2(v0, v1);
            *reinterpret_cast<float2*>(C + (size_t)(row + 8) * N + col) = make_float2(v2, v3);
        }
    }
}

// ---------------------------------------------------------------------------
extern "C" void kernel_launch(void* const* d_in, const int* in_sizes, int n_in,
                              void* d_out, int out_size)
{
    const float* x     = (const float*)d_in[0];
    const float* IFadj = (const float*)d_in[1];
    const float* adj   = (const float*)d_in[2];
    const float* W1    = (const float*)d_in[3];
    const float* b1    = (const float*)d_in[4];
    const float* W2    = (const float*)d_in[5];
    const float* b2    = (const float*)d_in[6];
    const float* bng   = (const float*)d_in[7];
    const float* bnb   = (const float*)d_in[8];
    const float* bnm   = (const float*)d_in[9];
    const float* bnv   = (const float*)d_in[10];
    float* out = (float*)d_out;

    float *s1, *h, *s2;
    cudaGetSymbolAddress((void**)&s1, g_S1);
    cudaGetSymbolAddress((void**)&h,  g_H);
    cudaGetSymbolAddress((void**)&s2, g_S2);

    const int smem = 2 * STAGE_BYTES;   // 128 KB dynamic
    cudaFuncSetAttribute(mma_gemm<0>, cudaFuncAttributeMaxDynamicSharedMemorySize, smem);
    cudaFuncSetAttribute(mma_gemm<1>, cudaFuncAttributeMaxDynamicSharedMemorySize, smem);
    cudaFuncSetAttribute(mma_gemm<2>, cudaFuncAttributeMaxDynamicSharedMemorySize, smem);

    const dim3 blk(512);

    // 1) S1 = x @ W1                      M=8192 N=512 K=1024
    mma_gemm<0><<<dim3(NHID / 128, N_NODES / 128), blk, smem>>>(
        x, W1, s1, N_NODES, NHID, NFEAT, nullptr, nullptr, nullptr, nullptr, nullptr);

    // 2) H = relu(IFadj @ S1 + b1)        M=8192 N=512 K=8192  (dominant)
    mma_gemm<1><<<dim3(NHID / 128, N_NODES / 128), blk, smem>>>(
        IFadj, s1, h, N_NODES, NHID, N_NODES, b1, nullptr, nullptr, nullptr, nullptr);

    // 3) S2 = H @ W2                      M=8192 N=256 K=512
    mma_gemm<0><<<dim3(OUTD / 128, N_NODES / 128), blk, smem>>>(
        h, W2, s2, N_NODES, OUTD, NHID, nullptr, nullptr, nullptr, nullptr, nullptr);

    // 4) out = BN(adj @ S2 + b2)          M=8192 N=256 K=8192
    mma_gemm<2><<<dim3(OUTD / 128, N_NODES / 128), blk, smem>>>(
        adj, s2, out, N_NODES, OUTD, N_NODES, b2, bng, bnb, bnm, bnv);
}

// round 17
// speedup vs baseline: 1.2651x; 1.1914x over previous
#include <cuda_runtime.h>
#include <cuda_fp16.h>
#include <cstdint>

// Problem constants
#define N_NODES 8192
#define NFEAT   1024
#define NHID    512
#define OUTD    256
#define BN_EPS  1e-5f

// Intermediates (allocation-free rule: device globals)
__device__ float g_S1[N_NODES * NHID];   // x @ W1
__device__ float g_H [N_NODES * NHID];   // relu(IFadj@S1 + b1)
__device__ float g_S2[N_NODES * OUTD];   // H @ W2

// ---------------------------------------------------------------------------
// helpers
// ---------------------------------------------------------------------------
__device__ __forceinline__ uint32_t smem_u32(const void* p) {
    uint32_t a;
    asm("{ .reg .u64 t; cvta.to.shared.u64 t, %1; cvt.u32.u64 %0, t; }"
        : "=r"(a) : "l"(p));
    return a;
}

// Swizzles (conflict-free ldmatrix):
// A tile: 128 rows x 128B (64 fp16 k). classic SW128: bits[4:6] ^= bits[7:9]
__device__ __forceinline__ uint32_t sw_a(uint32_t o) { return o ^ ((o >> 3) & 0x70); }
// B tile: 64 rows x 256B (128 fp16 n). bits[4:6] ^= bits[8:10]
__device__ __forceinline__ uint32_t sw_b(uint32_t o) { return o ^ ((o >> 4) & 0x70); }

__device__ __forceinline__ void ldsm_x4(uint32_t r[4], uint32_t addr) {
    asm volatile("ldmatrix.sync.aligned.m8n8.x4.shared.b16 {%0,%1,%2,%3}, [%4];"
        : "=r"(r[0]), "=r"(r[1]), "=r"(r[2]), "=r"(r[3]) : "r"(addr));
}
__device__ __forceinline__ void ldsm_x4_t(uint32_t r[4], uint32_t addr) {
    asm volatile("ldmatrix.sync.aligned.m8n8.x4.trans.shared.b16 {%0,%1,%2,%3}, [%4];"
        : "=r"(r[0]), "=r"(r[1]), "=r"(r[2]), "=r"(r[3]) : "r"(addr));
}

__device__ __forceinline__ void mma_f16(float* c, const uint32_t a[4],
                                        uint32_t b0, uint32_t b1) {
    asm volatile(
        "mma.sync.aligned.m16n8k16.row.col.f32.f16.f16.f32 "
        "{%0,%1,%2,%3}, {%4,%5,%6,%7}, {%8,%9}, {%0,%1,%2,%3};"
        : "+f"(c[0]), "+f"(c[1]), "+f"(c[2]), "+f"(c[3])
        : "r"(a[0]), "r"(a[1]), "r"(a[2]), "r"(a[3]), "r"(b0), "r"(b1));
}

// fp32 pair -> (hi, lo) fp16x2 split (hi = rn(x), lo = rn(x - hi))
__device__ __forceinline__ void split_pack_h(float a, float b, uint32_t& hi, uint32_t& lo) {
    __half2 h = __floats2half2_rn(a, b);
    float ra = a - __half2float(__low2half(h));
    float rb = b - __half2float(__high2half(h));
    __half2 l = __floats2half2_rn(ra, rb);
    hi = *reinterpret_cast<uint32_t*>(&h);
    lo = *reinterpret_cast<uint32_t*>(&l);
}
// fp32 pair -> fp16x2 (single rounding, for B)
__device__ __forceinline__ uint32_t pack_h(float a, float b) {
    __half2 h = __floats2half2_rn(a, b);
    return *reinterpret_cast<uint32_t*>(&h);
}

// ---------------------------------------------------------------------------
// Warp-specialized fp16 2-PRODUCT split GEMM.
// C[M,N] = A[M,K] @ B[K,N] (fp32 in/out):
//   A = Ah + Al (fp16 hi/lo, ~22-bit effective), B = fp16 (11-bit).
//   C ~= Ah@Bh + Al@Bh    -- only B's 2^-11 rounding survives (~2.8e-4/GEMM).
// vs bf16 3-product: MMAs x0.67, LDSM 12->10, SMEM stage 64->48KB.
// CTA tile 128x128, BK=64, 512 threads:
//   warps 0-7 : CONSUMERS, warp tile 64x32 (2M x 4N), reg-level frag
//               double-buffering (next k-step's LDSMs issued before MMAs)
//   warps 8-15: PRODUCERS, LDG fp32 -> convert -> STS
// Double-buffered SMEM (2 x 48KB), one __syncthreads per K-chunk.
// EPI 0: none | 1: relu(+bias) | 2: BatchNorm eval (+bias)
// ---------------------------------------------------------------------------
#define STAGE_BYTES 49152   // Ahi 16K | Alo 16K | Bh 16K

template<int EPI>
__global__ __launch_bounds__(512, 1)
void mma_gemm(const float* __restrict__ A, const float* __restrict__ B,
              float* __restrict__ C, int M, int N, int K,
              const float* __restrict__ bias,
              const float* __restrict__ bng, const float* __restrict__ bnb,
              const float* __restrict__ bnm, const float* __restrict__ bnv)
{
    extern __shared__ __align__(128) char smc[];   // 96 KB: 2 stages
    const uint32_t sbase = smem_u32(smc);

    const int tid  = threadIdx.x;
    const int lane = tid & 31;
    const int wid  = tid >> 5;
    const bool is_consumer = (wid < 8);
    const int rowBase = blockIdx.y * 128;
    const int colBase = blockIdx.x * 128;
    const int nk = K >> 6;   // K / 64

    if (!is_consumer) {
        // =========================== PRODUCER ===============================
        const int ptid = tid - 256;            // 0..255
        float4 stA[8];                          // A: 128m x 64k fp32
        float4 stB[4][2];                       // B: 64k x 128n fp32

        auto ldg = [&](int k0) {
#pragma unroll
            for (int s = 0; s < 8; s++) {
                const int idx = (ptid + s * 256) * 4;
                const int m = idx >> 6, k = idx & 63;
                stA[s] = *reinterpret_cast<const float4*>(
                    A + (size_t)(rowBase + m) * K + k0 + k);
            }
#pragma unroll
            for (int s = 0; s < 4; s++) {
                const int idx = (ptid + s * 256) * 8;
                const int k = idx >> 7, n = idx & 127;
                const float* p = B + (size_t)(k0 + k) * N + colBase + n;
                stB[s][0] = *reinterpret_cast<const float4*>(p);
                stB[s][1] = *reinterpret_cast<const float4*>(p + 4);
            }
        };

        auto sts = [&](int buf) {
            char* base = smc + buf * STAGE_BYTES;
#pragma unroll
            for (int s = 0; s < 8; s++) {
                const int idx = (ptid + s * 256) * 4;
                const int m = idx >> 6, k = idx & 63;
                uint32_t h0, l0, h1, l1;
                split_pack_h(stA[s].x, stA[s].y, h0, l0);
                split_pack_h(stA[s].z, stA[s].w, h1, l1);
                const uint32_t off = sw_a((uint32_t)(m * 128 + k * 2)); // 8B aligned
                *reinterpret_cast<uint2*>(base + off)         = make_uint2(h0, h1);
                *reinterpret_cast<uint2*>(base + 16384 + off) = make_uint2(l0, l1);
            }
#pragma unroll
            for (int s = 0; s < 4; s++) {
                const int idx = (ptid + s * 256) * 8;
                const int k = idx >> 7, n = idx & 127;
                const uint32_t off = sw_b((uint32_t)(k * 256 + n * 2)); // 16B aligned
                *reinterpret_cast<uint4*>(base + 32768 + off) = make_uint4(
                    pack_h(stB[s][0].x, stB[s][0].y), pack_h(stB[s][0].z, stB[s][0].w),
                    pack_h(stB[s][1].x, stB[s][1].y), pack_h(stB[s][1].z, stB[s][1].w));
            }
        };

        ldg(0);
        sts(0);
        __syncthreads();
        for (int it = 0; it < nk; it++) {
            if (it + 1 < nk) {
                ldg((it + 1) << 6);
                sts((it + 1) & 1);   // other buffer: consumers read it&1 now
            }
            __syncthreads();
        }
        return;   // producers skip the epilogue
    }

    // ============================= CONSUMER ==================================
    const int wm = (wid >> 2) * 64;    // warp M offset (0 or 64)
    const int wn = (wid & 3) * 32;     // warp N offset (0/32/64/96)

    float acc[4][4][4];                 // 64 regs
#pragma unroll
    for (int i = 0; i < 4; i++)
#pragma unroll
        for (int j = 0; j < 4; j++)
#pragma unroll
            for (int r = 0; r < 4; r++) acc[i][j][r] = 0.f;

    // Fragment double-buffer: [pb][...]  (af: A hi/lo, bh: B)
    uint32_t af[2][2][4][4];   // 64 regs
    uint32_t bh[2][2][4];      // 16 regs

    // lane-constant addressing pieces
    const int m_lane   = lane & 15;
    const int ka_lane  = (lane >> 4) << 3;          // A: k sub-offset
    const int mat      = lane >> 3, wi = lane & 7;
    const int kb_lane  = (mat & 1) * 8 + wi;        // B: k sub-offset
    const int nb0      = wn + (mat >> 1) * 8;       // B: n base for grp 0

    __syncthreads();   // matches producers' post-prologue barrier
    for (int it = 0; it < nk; it++) {
        const int buf = it & 1;
        const uint32_t sA_hi = sbase + buf * STAGE_BYTES;
        const uint32_t sA_lo = sA_hi + 16384;
        const uint32_t sB_hi = sA_hi + 32768;

        // prefetch k-step 0 fragments into buffer 0
#pragma unroll
        for (int mf = 0; mf < 4; mf++) {
            const uint32_t off = sw_a(
                (uint32_t)((wm + mf * 16 + m_lane) * 128 + ka_lane * 2));
            ldsm_x4(af[0][0][mf], sA_hi + off);
            ldsm_x4(af[0][1][mf], sA_lo + off);
        }
#pragma unroll
        for (int grp = 0; grp < 2; grp++) {
            const uint32_t boff = sw_b(
                (uint32_t)(kb_lane * 256 + (nb0 + grp * 16) * 2));
            ldsm_x4_t(bh[0][grp], sB_hi + boff);
        }

#pragma unroll
        for (int ks = 0; ks < 4; ks++) {
            const int pb = ks & 1;
            // prefetch NEXT k-step's fragments before this step's MMAs
            if (ks < 3) {
                const int nb = pb ^ 1;
                const int k1 = (ks + 1) * 16;
#pragma unroll
                for (int mf = 0; mf < 4; mf++) {
                    const uint32_t off = sw_a(
                        (uint32_t)((wm + mf * 16 + m_lane) * 128 + (k1 + ka_lane) * 2));
                    ldsm_x4(af[nb][0][mf], sA_hi + off);
                    ldsm_x4(af[nb][1][mf], sA_lo + off);
                }
#pragma unroll
                for (int grp = 0; grp < 2; grp++) {
                    const uint32_t boff = sw_b(
                        (uint32_t)((k1 + kb_lane) * 256 + (nb0 + grp * 16) * 2));
                    ldsm_x4_t(bh[nb][grp], sB_hi + boff);
                }
            }
            // 32 MMAs on the CURRENT buffer (LDSMs above retire underneath)
#pragma unroll
            for (int mf = 0; mf < 4; mf++)
#pragma unroll
                for (int nf = 0; nf < 4; nf++) {
                    const int g = nf >> 1, q = (nf & 1) * 2;
                    mma_f16(acc[mf][nf], af[pb][0][mf], bh[pb][g][q], bh[pb][g][q + 1]);
                }
#pragma unroll
            for (int mf = 0; mf < 4; mf++)
#pragma unroll
                for (int nf = 0; nf < 4; nf++) {
                    const int g = nf >> 1, q = (nf & 1) * 2;
                    mma_f16(acc[mf][nf], af[pb][1][mf], bh[pb][g][q], bh[pb][g][q + 1]);
                }
        }
        __syncthreads();
    }

    // ---- epilogue (consumers only) ----
    const int g   = lane >> 2;
    const int tig = lane & 3;
#pragma unroll
    for (int mf = 0; mf < 4; mf++) {
#pragma unroll
        for (int nf = 0; nf < 4; nf++) {
            const int row = rowBase + wm + mf * 16 + g;
            const int col = colBase + wn + nf * 8 + tig * 2;
            float v0 = acc[mf][nf][0], v1 = acc[mf][nf][1];
            float v2 = acc[mf][nf][2], v3 = acc[mf][nf][3];
            if constexpr (EPI >= 1) {
                const float b0 = bias[col], b1 = bias[col + 1];
                v0 += b0; v1 += b1; v2 += b0; v3 += b1;
            }
            if constexpr (EPI == 1) {
                v0 = fmaxf(v0, 0.f); v1 = fmaxf(v1, 0.f);
                v2 = fmaxf(v2, 0.f); v3 = fmaxf(v3, 0.f);
            }
            if constexpr (EPI == 2) {
                const float i0 = bng[col]     * rsqrtf(bnv[col]     + BN_EPS);
                const float i1 = bng[col + 1] * rsqrtf(bnv[col + 1] + BN_EPS);
                const float a0 = bnb[col]     - bnm[col]     * i0;
                const float a1 = bnb[col + 1] - bnm[col + 1] * i1;
                v0 = v0 * i0 + a0; v1 = v1 * i1 + a1;
                v2 = v2 * i0 + a0; v3 = v3 * i1 + a1;
            }
            *reinterpret_cast<float2*>(C + (size_t)row * N + col)       = make_float2(v0, v1);
            *reinterpret_cast<float2*>(C + (size_t)(row + 8) * N + col) = make_float2(v2, v3);
        }
    }
}

// ---------------------------------------------------------------------------
extern "C" void kernel_launch(void* const* d_in, const int* in_sizes, int n_in,
                              void* d_out, int out_size)
{
    const float* x     = (const float*)d_in[0];
    const float* IFadj = (const float*)d_in[1];
    const float* adj   = (const float*)d_in[2];
    const float* W1    = (const float*)d_in[3];
    const float* b1    = (const float*)d_in[4];
    const float* W2    = (const float*)d_in[5];
    const float* b2    = (const float*)d_in[6];
    const float* bng   = (const float*)d_in[7];
    const float* bnb   = (const float*)d_in[8];
    const float* bnm   = (const float*)d_in[9];
    const float* bnv   = (const float*)d_in[10];
    float* out = (float*)d_out;

    float *s1, *h, *s2;
    cudaGetSymbolAddress((void**)&s1, g_S1);
    cudaGetSymbolAddress((void**)&h,  g_H);
    cudaGetSymbolAddress((void**)&s2, g_S2);

    const int smem = 2 * STAGE_BYTES;   // 96 KB dynamic
    cudaFuncSetAttribute(mma_gemm<0>, cudaFuncAttributeMaxDynamicSharedMemorySize, smem);
    cudaFuncSetAttribute(mma_gemm<1>, cudaFuncAttributeMaxDynamicSharedMemorySize, smem);
    cudaFuncSetAttribute(mma_gemm<2>, cudaFuncAttributeMaxDynamicSharedMemorySize, smem);

    const dim3 blk(512);

    // 1) S1 = x @ W1                      M=8192 N=512 K=1024
    mma_gemm<0><<<dim3(NHID / 128, N_NODES / 128), blk, smem>>>(
        x, W1, s1, N_NODES, NHID, NFEAT, nullptr, nullptr, nullptr, nullptr, nullptr);

    // 2) H = relu(IFadj @ S1 + b1)        M=8192 N=512 K=8192  (dominant)
    mma_gemm<1><<<dim3(NHID / 128, N_NODES / 128), blk, smem>>>(
        IFadj, s1, h, N_NODES, NHID, N_NODES, b1, nullptr, nullptr, nullptr, nullptr);

    // 3) S2 = H @ W2                      M=8192 N=256 K=512
    mma_gemm<0><<<dim3(OUTD / 128, N_NODES / 128), blk, smem>>>(
        h, W2, s2, N_NODES, OUTD, NHID, nullptr, nullptr, nullptr, nullptr, nullptr);

    // 4) out = BN(adj @ S2 + b2)          M=8192 N=256 K=8192
    mma_gemm<2><<<dim3(OUTD / 128, N_NODES / 128), blk, smem>>>(
        adj, s2, out, N_NODES, OUTD, N_NODES, b2, bng, bnb, bnm, bnv);
}